// round 4
// baseline (speedup 1.0000x reference)
#include <cuda_runtime.h>
#include <cuda_bf16.h>
#include <math.h>

// ---------------------------------------------------------------------------
// AttentionClassificationHead — GB300, round 4
// bf16-split tensor-core GEMMs; activations stored PRE-SPLIT in smem;
// 512 threads/CTA (16 warps), 32 windows/CTA, B weights [col][k2] + LDG ring.
// B=64, N=512, T=6, E=256, H=4, hd=64, BN=32768
// ---------------------------------------------------------------------------

__device__ float g_weff[1024];       // [4][256]
__device__ float g_ceff[4];
// Weight fragments, col-major: uint2 = (hi bf16 pair, lo bf16 pair) per k2
__device__ uint2 g_B1[32768];        // [4*64 cols][128 k2]
__device__ uint2 g_B2[32768];        // [256 cols][128 k2]
__device__ uint2 g_B3[16384];        // [128 cols][128 k2]

// Shared memory float offsets
#define W0   0              // 1028: weff + ceff (phase 1 only)
#define XA0  1056           // xbar split uint2 [32][526] = 33664 floats
#define BB0  1056           // fp32 [32][264] (aliases XA, live after GEMM2)
#define G30  1056           // fp32 [32][136] (aliases, live after GEMM3)
#define BA0  34720          // split uint2 [32][130] = 8320 floats
#define MB0  43040          // 32 ints
#define SFLOATS 43072
#define SMEM_BYTES (SFLOATS * 4)
#define XST2 526            // xbar row stride in uint2 (2-phase conflict-free)
#define BAST2 130           // bufA row stride in uint2
#define BBST 264            // fp32 buf stride
#define G3ST 136            // GEMM3 out stride

__device__ __forceinline__ float gelu_exact(float v) {
    return 0.5f * v * (1.0f + erff(v * 0.70710678118654752f));
}

// rn split of (a,b) into (hi bf16x2, lo bf16x2); low half = a (even k)
__device__ __forceinline__ uint2 split_pack2(float a, float b) {
    unsigned hi, lo;
    asm("cvt.rn.bf16x2.f32 %0, %1, %2;" : "=r"(hi) : "f"(b), "f"(a));
    float la = a - __uint_as_float(hi << 16);
    float lb = b - __uint_as_float(hi & 0xffff0000u);
    asm("cvt.rn.bf16x2.f32 %0, %1, %2;" : "=r"(lo) : "f"(lb), "f"(la));
    return make_uint2(hi, lo);
}

__device__ __forceinline__ void mma16816(float* c, const unsigned* a,
                                         unsigned b0, unsigned b1) {
    asm("mma.sync.aligned.m16n8k16.row.col.f32.bf16.bf16.f32 "
        "{%0,%1,%2,%3}, {%4,%5,%6,%7}, {%8,%9}, {%0,%1,%2,%3};"
        : "+f"(c[0]), "+f"(c[1]), "+f"(c[2]), "+f"(c[3])
        : "r"(a[0]), "r"(a[1]), "r"(a[2]), "r"(a[3]), "r"(b0), "r"(b1));
}

// ---------------------------------------------------------------------------
// Prep: weff/ceff + split-bf16 col-major weights.
// ---------------------------------------------------------------------------
__global__ void ach_prep(const float* __restrict__ query,
                         const float* __restrict__ ipw,
                         const float* __restrict__ ipb,
                         const float* __restrict__ outw,
                         const float* __restrict__ w1) {
    __shared__ float qs[256];
    int tid = threadIdx.x;
    {
        float a = ipb[tid];
        for (int e = 0; e < 256; e++) a += query[e] * ipw[tid * 256 + e];
        qs[tid] = a;
    }
    __syncthreads();
    const int N1 = 1024, N2 = N1 + 32768, N3 = N2 + 32768, N4 = N3 + 16384;
    const int NT = N4 + 4;
    for (int idx = blockIdx.x * 256 + tid; idx < NT; idx += gridDim.x * 256) {
        if (idx < N1) {
            int h = idx >> 8, e = idx & 255;
            float s = 0.f;
            for (int d = 0; d < 64; d++)
                s += qs[h * 64 + d] * ipw[(256 + h * 64 + d) * 256 + e];
            g_weff[idx] = s;
        } else if (idx < N2) {
            int j = idx - N1, n = j >> 7, k2 = j & 127;
            const float* src = ipw + (512 + n) * 256 + 2 * k2;
            g_B1[j] = split_pack2(src[0], src[1]);
        } else if (idx < N3) {
            int j = idx - N2, n = j >> 7, k2 = j & 127;
            const float* src = outw + n * 256 + 2 * k2;
            g_B2[j] = split_pack2(src[0], src[1]);
        } else if (idx < N4) {
            int j = idx - N3, n = j >> 7, k2 = j & 127;
            const float* src = w1 + n * 256 + 2 * k2;
            g_B3[j] = split_pack2(src[0], src[1]);
        } else {
            int h = idx - N4;
            float s = 0.f;
            for (int d = 0; d < 64; d++)
                s += qs[h * 64 + d] * ipb[256 + h * 64 + d];
            g_ceff[h] = s;
        }
    }
}

// ---------------------------------------------------------------------------
// MMA GEMM: per warp M=32 x (NT*8 cols) x K=256. A pre-split in smem,
// B [col][128] from L2 via depth-2 LDG ring. OM: 0=fp32, 1=split, 2=gelu fp32
// ---------------------------------------------------------------------------
template <int NT, int OM>
__device__ __forceinline__ void gemm_mma(const uint2* __restrict__ Asm, int Ast2,
                                         const uint2* __restrict__ Bg, int nb0,
                                         const float* __restrict__ bias,
                                         int outcol0,
                                         float* __restrict__ outf, int ofst,
                                         uint2* __restrict__ outs, int ost2) {
    const int lane = threadIdx.x & 31;
    const int g = lane >> 2, t = lane & 3;

    float acc[2][NT][4];
#pragma unroll
    for (int nt = 0; nt < NT; nt++) {
        float b0 = bias[nb0 + nt * 8 + 2 * t];
        float b1 = bias[nb0 + nt * 8 + 2 * t + 1];
#pragma unroll
        for (int mi = 0; mi < 2; mi++) {
            acc[mi][nt][0] = b0; acc[mi][nt][1] = b1;
            acc[mi][nt][2] = b0; acc[mi][nt][3] = b1;
        }
    }

    const uint2* bp[NT];
#pragma unroll
    for (int nt = 0; nt < NT; nt++)
        bp[nt] = Bg + (nb0 + nt * 8 + g) * 128 + t;

    uint2 Bb[3][NT][2];
#pragma unroll
    for (int p = 0; p < 2; p++)
#pragma unroll
        for (int nt = 0; nt < NT; nt++) {
            Bb[p][nt][0] = __ldg(bp[nt] + p * 8);
            Bb[p][nt][1] = __ldg(bp[nt] + p * 8 + 4);
        }

#pragma unroll
    for (int kt = 0; kt < 16; kt++) {
        if (kt + 2 < 16) {
#pragma unroll
            for (int nt = 0; nt < NT; nt++) {
                Bb[(kt + 2) % 3][nt][0] = __ldg(bp[nt] + (kt + 2) * 8);
                Bb[(kt + 2) % 3][nt][1] = __ldg(bp[nt] + (kt + 2) * 8 + 4);
            }
        }
#pragma unroll
        for (int mi = 0; mi < 2; mi++) {
            const uint2* ar = Asm + (mi * 16 + g) * Ast2 + kt * 8 + t;
            uint2 u0 = ar[0];
            uint2 u1 = ar[8 * Ast2];
            uint2 u2 = ar[4];
            uint2 u3 = ar[8 * Ast2 + 4];
            unsigned Ah[4] = {u0.x, u1.x, u2.x, u3.x};
            unsigned Al[4] = {u0.y, u1.y, u2.y, u3.y};
#pragma unroll
            for (int nt = 0; nt < NT; nt++) {
                uint2 b0 = Bb[kt % 3][nt][0], b1 = Bb[kt % 3][nt][1];
                mma16816(acc[mi][nt], Ah, b0.x, b1.x);
                mma16816(acc[mi][nt], Ah, b0.y, b1.y);
                mma16816(acc[mi][nt], Al, b0.x, b1.x);
            }
        }
    }

#pragma unroll
    for (int mi = 0; mi < 2; mi++)
#pragma unroll
        for (int nt = 0; nt < NT; nt++) {
            float c0 = acc[mi][nt][0], c1 = acc[mi][nt][1];
            float c2 = acc[mi][nt][2], c3 = acc[mi][nt][3];
            int r0 = mi * 16 + g, r1 = r0 + 8;
            if (OM == 1) {
                int k2o = (outcol0 >> 1) + nt * 4 + t;
                outs[r0 * ost2 + k2o] = split_pack2(c0, c1);
                outs[r1 * ost2 + k2o] = split_pack2(c2, c3);
            } else {
                if (OM == 2) {
                    c0 = gelu_exact(c0); c1 = gelu_exact(c1);
                    c2 = gelu_exact(c2); c3 = gelu_exact(c3);
                }
                int col = outcol0 + nt * 8 + 2 * t;
                *(float2*)&outf[r0 * ofst + col] = make_float2(c0, c1);
                *(float2*)&outf[r1 * ofst + col] = make_float2(c2, c3);
            }
        }
}

// ---------------------------------------------------------------------------
// Main kernel: 1024 CTAs x 512 threads, 32 windows per CTA.
// ---------------------------------------------------------------------------
__global__ void __launch_bounds__(512, 1)
ach_main(const float* __restrict__ x, const int* __restrict__ mask,
         const float* __restrict__ ipb, const float* __restrict__ out_b,
         const float* __restrict__ ln_g, const float* __restrict__ ln_b,
         const float* __restrict__ b1, const float* __restrict__ w2,
         const float* __restrict__ b2, float* __restrict__ out) {
    extern __shared__ float S[];
    uint2* XA = (uint2*)&S[XA0];
    uint2* BA = (uint2*)&S[BA0];
    const int tid = threadIdx.x;
    const int lane = tid & 31;
    const int wid = tid >> 5;
    const int bn0 = blockIdx.x << 5;

    for (int i = tid; i < 1024; i += 512) S[W0 + i] = g_weff[i];
    if (tid < 4) S[W0 + 1024 + tid] = g_ceff[tid];
    __syncthreads();

    // ---- Phase 1: 2 windows per warp — scores, softmax, xbar (split) ----
#pragma unroll
    for (int rep = 0; rep < 2; rep++) {
        const int w = wid * 2 + rep;
        const long bn = (long)bn0 + w;
        const float4* xp = (const float4*)(x + bn * 1536);
        float4 xa[6], xc[6];
#pragma unroll
        for (int t = 0; t < 6; t++) {
            xa[t] = xp[t * 64 + lane];
            xc[t] = xp[t * 64 + 32 + lane];
        }
        int mv = (lane < 6) ? mask[bn * 6 + lane] : 0;
        unsigned mb = __ballot_sync(0xffffffffu, mv != 0) & 0x3fu;
        if (lane == 0) ((int*)S)[MB0 + w] = (int)mb;

        float aw[4][6];
#pragma unroll
        for (int h = 0; h < 4; h++) {
            const float4* wf = (const float4*)&S[W0 + h * 256];
            float4 wa = wf[lane], wc = wf[32 + lane];
            float ce = S[W0 + 1024 + h];
            float sc[6];
#pragma unroll
            for (int t = 0; t < 6; t++) {
                float p = xa[t].x * wa.x + xa[t].y * wa.y + xa[t].z * wa.z +
                          xa[t].w * wa.w + xc[t].x * wc.x + xc[t].y * wc.y +
                          xc[t].z * wc.z + xc[t].w * wc.w;
#pragma unroll
                for (int o = 16; o > 0; o >>= 1)
                    p += __shfl_xor_sync(0xffffffffu, p, o);
                sc[t] = ((mb >> t) & 1u) ? (p + ce) * 0.125f : -1e9f;
            }
            float m = sc[0];
#pragma unroll
            for (int t = 1; t < 6; t++) m = fmaxf(m, sc[t]);
            float s = 0.f;
#pragma unroll
            for (int t = 0; t < 6; t++) { aw[h][t] = expf(sc[t] - m); s += aw[h][t]; }
            float inv = 1.0f / s;
#pragma unroll
            for (int t = 0; t < 6; t++) aw[h][t] *= inv;
        }
#pragma unroll
        for (int h = 0; h < 4; h++) {
            float4 A = make_float4(0.f, 0.f, 0.f, 0.f);
            float4 C = make_float4(0.f, 0.f, 0.f, 0.f);
#pragma unroll
            for (int t = 0; t < 6; t++) {
                float a = aw[h][t];
                A.x += a * xa[t].x; A.y += a * xa[t].y;
                A.z += a * xa[t].z; A.w += a * xa[t].w;
                C.x += a * xc[t].x; C.y += a * xc[t].y;
                C.z += a * xc[t].z; C.w += a * xc[t].w;
            }
            uint2 p0 = split_pack2(A.x, A.y), p1 = split_pack2(A.z, A.w);
            uint2 p2 = split_pack2(C.x, C.y), p3 = split_pack2(C.z, C.w);
            *(uint4*)&XA[w * XST2 + h * 128 + 2 * lane] =
                make_uint4(p0.x, p0.y, p1.x, p1.y);
            *(uint4*)&XA[w * XST2 + h * 128 + 64 + 2 * lane] =
                make_uint4(p2.x, p2.y, p3.x, p3.y);
        }
    }
    __syncthreads();

    // ---- GEMM1 (block-diag by head): xbar -> bufA (split) ----
    {
        const int h = wid >> 2, q = wid & 3;
        gemm_mma<2, 1>(XA + h * 128, XST2, g_B1 + h * 64 * 128, q * 16,
                       ipb + 512 + h * 64, h * 64 + q * 16,
                       nullptr, 0, BA, BAST2);
    }
    __syncthreads();
    // ---- GEMM2: bufA -> bufB fp32 ----
    gemm_mma<2, 0>(BA, BAST2, g_B2, wid * 16, out_b, wid * 16,
                   &S[BB0], BBST, nullptr, 0);
    __syncthreads();

    // ---- LayerNorm: bufB fp32 -> bufA (split). Lane owns 8 consecutive ----
#pragma unroll
    for (int rep = 0; rep < 2; rep++) {
        const int w = wid * 2 + rep;
        float4 va = *(const float4*)&S[BB0 + w * BBST + lane * 8];
        float4 vb = *(const float4*)&S[BB0 + w * BBST + lane * 8 + 4];
        float s = va.x + va.y + va.z + va.w + vb.x + vb.y + vb.z + vb.w;
        float s2 = va.x * va.x + va.y * va.y + va.z * va.z + va.w * va.w +
                   vb.x * vb.x + vb.y * vb.y + vb.z * vb.z + vb.w * vb.w;
#pragma unroll
        for (int o = 16; o > 0; o >>= 1) {
            s  += __shfl_xor_sync(0xffffffffu, s, o);
            s2 += __shfl_xor_sync(0xffffffffu, s2, o);
        }
        float mu = s * (1.0f / 256.0f);
        float var = s2 * (1.0f / 256.0f) - mu * mu;
        float rstd = rsqrtf(var + 1e-5f);
        float y[8];
        float vv[8] = {va.x, va.y, va.z, va.w, vb.x, vb.y, vb.z, vb.w};
#pragma unroll
        for (int j = 0; j < 8; j++) {
            int o = lane * 8 + j;
            y[j] = (vv[j] - mu) * rstd * ln_g[o] + ln_b[o];
        }
        uint2 p0 = split_pack2(y[0], y[1]), p1 = split_pack2(y[2], y[3]);
        uint2 p2 = split_pack2(y[4], y[5]), p3 = split_pack2(y[6], y[7]);
        *(uint4*)&BA[w * BAST2 + lane * 4] = make_uint4(p0.x, p0.y, p1.x, p1.y);
        *(uint4*)&BA[w * BAST2 + lane * 4 + 2] = make_uint4(p2.x, p2.y, p3.x, p3.y);
    }
    __syncthreads();

    // ---- GEMM3: fc1 + exact GELU: bufA -> G3 fp32 ----
    gemm_mma<1, 2>(BA, BAST2, g_B3, wid * 8, b1, wid * 8,
                   &S[G30], G3ST, nullptr, 0);
    __syncthreads();

    // ---- Final dot with w2, zero invalid windows ----
#pragma unroll
    for (int rep = 0; rep < 2; rep++) {
        const int w = wid * 2 + rep;
        float r = 0.f;
#pragma unroll
        for (int j = 0; j < 4; j++) {
            int o = lane + 32 * j;
            r += S[G30 + w * G3ST + o] * w2[o];
        }
#pragma unroll
        for (int o = 16; o > 0; o >>= 1)
            r += __shfl_xor_sync(0xffffffffu, r, o);
        if (lane == 0) {
            int mb = ((int*)S)[MB0 + w];
            out[bn0 + w] = mb ? (r + b2[0]) : 0.0f;
        }
    }
}

// ---------------------------------------------------------------------------
extern "C" void kernel_launch(void* const* d_in, const int* in_sizes, int n_in,
                              void* d_out, int out_size) {
    (void)in_sizes; (void)n_in; (void)out_size;
    const float* x    = (const float*)d_in[0];
    const int*   mask = (const int*)d_in[1];
    const float* query= (const float*)d_in[2];
    const float* ipw  = (const float*)d_in[3];
    const float* ipb  = (const float*)d_in[4];
    const float* outw = (const float*)d_in[5];
    const float* outb = (const float*)d_in[6];
    const float* ln_g = (const float*)d_in[7];
    const float* ln_b = (const float*)d_in[8];
    const float* w1   = (const float*)d_in[9];
    const float* b1   = (const float*)d_in[10];
    const float* w2   = (const float*)d_in[11];
    const float* b2   = (const float*)d_in[12];
    float* out = (float*)d_out;

    cudaFuncSetAttribute(ach_main, cudaFuncAttributeMaxDynamicSharedMemorySize,
                         SMEM_BYTES);

    ach_prep<<<256, 256>>>(query, ipw, ipb, outw, w1);
    ach_main<<<1024, 512, SMEM_BYTES>>>(x, mask, ipb, outb, ln_g, ln_b, b1, w2,
                                        b2, out);
}

// round 5
// speedup vs baseline: 1.4675x; 1.4675x over previous
#include <cuda_runtime.h>
#include <cuda_bf16.h>
#include <math.h>

// ---------------------------------------------------------------------------
// AttentionClassificationHead — GB300, round 5
// bf16-split MMA; activations pre-split in smem; M-split warps (2x8);
// B weights fragment-packed uint4 [colgrp][kt][col][t] for 512B/warp LDGs.
// B=64, N=512, T=6, E=256, H=4, hd=64, BN=32768; 32 windows/CTA, 512 thr.
// ---------------------------------------------------------------------------

__device__ float g_weff[1024];       // [4][256]
__device__ float g_ceff[4];
// uint4 = (hi_k2=kt*8+t, hi_k2=kt*8+t+4, lo_t, lo_t+4) per (col, kt)
__device__ uint4 g_B1[16384];        // 256 cols (4 heads x 64)
__device__ uint4 g_B2[16384];        // 256 cols
__device__ uint4 g_B3[8192];         // 128 cols

// Shared memory float offsets
#define W0   0              // 1028: weff + ceff (phase 1 only)
#define XA0  1056           // xbar split uint2 [32][524] = 33536 floats
#define BB0  1056           // fp32 [32][264] (aliases XA, live after GEMM2)
#define G30  1056           // fp32 [32][136] (aliases, live after GEMM3)
#define BA0  34592          // split uint2 [32][132] = 8448 floats
#define MB0  43040          // 32 ints
#define SFLOATS 43072
#define SMEM_BYTES (SFLOATS * 4)
#define XST2 524            // xbar row stride (uint2); row step 96 mod 128B
#define BAST2 132           // bufA row stride (uint2); row step 32 mod 128B
#define BBST 264            // fp32 buf stride; 1056B, 32 mod 128
#define G3ST 136            // fp32; 544B, 32 mod 128

__device__ __forceinline__ float gelu_exact(float v) {
    return 0.5f * v * (1.0f + erff(v * 0.70710678118654752f));
}

// rn split of (a,b) into (hi bf16x2, lo bf16x2); low half = a (even k)
__device__ __forceinline__ uint2 split_pack2(float a, float b) {
    unsigned hi, lo;
    asm("cvt.rn.bf16x2.f32 %0, %1, %2;" : "=r"(hi) : "f"(b), "f"(a));
    float la = a - __uint_as_float(hi << 16);
    float lb = b - __uint_as_float(hi & 0xffff0000u);
    asm("cvt.rn.bf16x2.f32 %0, %1, %2;" : "=r"(lo) : "f"(lb), "f"(la));
    return make_uint2(hi, lo);
}

__device__ __forceinline__ void mma16816(float* c, const unsigned* a,
                                         unsigned b0, unsigned b1) {
    asm("mma.sync.aligned.m16n8k16.row.col.f32.bf16.bf16.f32 "
        "{%0,%1,%2,%3}, {%4,%5,%6,%7}, {%8,%9}, {%0,%1,%2,%3};"
        : "+f"(c[0]), "+f"(c[1]), "+f"(c[2]), "+f"(c[3])
        : "r"(a[0]), "r"(a[1]), "r"(a[2]), "r"(a[3]), "r"(b0), "r"(b1));
}

// ---------------------------------------------------------------------------
// prep0 (1 block): q projection, weff, ceff
// ---------------------------------------------------------------------------
__global__ void ach_prep0(const float* __restrict__ query,
                          const float* __restrict__ ipw,
                          const float* __restrict__ ipb) {
    __shared__ float qs[256];
    int tid = threadIdx.x;
    {
        float a = ipb[tid];
        for (int e = 0; e < 256; e++) a += query[e] * ipw[tid * 256 + e];
        qs[tid] = a;
    }
    __syncthreads();
    for (int idx = tid; idx < 1024; idx += 256) {
        int h = idx >> 8, e = idx & 255;
        float s = 0.f;
        for (int d = 0; d < 64; d++)
            s += qs[h * 64 + d] * ipw[(256 + h * 64 + d) * 256 + e];
        g_weff[idx] = s;
    }
    if (tid < 4) {
        float s = 0.f;
        for (int d = 0; d < 64; d++)
            s += qs[tid * 64 + d] * ipb[256 + tid * 64 + d];
        g_ceff[tid] = s;
    }
}

// ---------------------------------------------------------------------------
// prep1 (160 blocks x 256): fragment-pack the three weight matrices.
// ---------------------------------------------------------------------------
__global__ void ach_prep1(const float* __restrict__ ipw,
                          const float* __restrict__ outw,
                          const float* __restrict__ w1) {
    int idx = blockIdx.x * 256 + threadIdx.x;   // 0..40959
    const float* base;
    uint4* dst;
    int j;
    if (idx < 16384)      { j = idx;         base = ipw + 512 * 256; dst = g_B1; }
    else if (idx < 32768) { j = idx - 16384; base = outw;            dst = g_B2; }
    else                  { j = idx - 32768; base = w1;              dst = g_B3; }
    int t = j & 3, cc = (j >> 2) & 7, kt = (j >> 5) & 15, cg = j >> 9;
    int col = cg * 8 + cc;
    int kA = kt * 16 + 2 * t;           // k index (even)
    const float* row = base + col * 256;
    uint2 p = split_pack2(row[kA],     row[kA + 1]);
    uint2 q = split_pack2(row[kA + 8], row[kA + 9]);
    dst[j] = make_uint4(p.x, q.x, p.y, q.y);
}

// ---------------------------------------------------------------------------
// MMA GEMM: per warp M=16 (rows m0..m0+15) x NT*8 cols x K=256.
// A pre-split uint2 in smem; B uint4 fragments from L2, depth-2 ring.
// OM: 0 = fp32 out, 1 = split out, 2 = gelu fp32 out.
// ---------------------------------------------------------------------------
template <int NT, int OM>
__device__ __forceinline__ void gemm_mma(const uint2* __restrict__ Asm, int Ast2,
                                         int m0,
                                         const uint4* __restrict__ Bg, int cg0,
                                         const float* __restrict__ bias,
                                         int outcol0,
                                         float* __restrict__ outf, int ofst,
                                         uint2* __restrict__ outs, int ost2) {
    const int lane = threadIdx.x & 31;
    const int g = lane >> 2, t = lane & 3;

    float acc[NT][4];
#pragma unroll
    for (int nt = 0; nt < NT; nt++) {
        float b0 = bias[outcol0 + nt * 8 + 2 * t];
        float b1 = bias[outcol0 + nt * 8 + 2 * t + 1];
        acc[nt][0] = b0; acc[nt][1] = b1; acc[nt][2] = b0; acc[nt][3] = b1;
    }

    const uint4* bp = Bg + (size_t)cg0 * 512 + lane;   // nt: +512, kt: +32
    uint4 Bb[2][NT];
#pragma unroll
    for (int nt = 0; nt < NT; nt++) Bb[0][nt] = __ldg(bp + nt * 512);

#pragma unroll
    for (int kt = 0; kt < 16; kt++) {
        if (kt + 1 < 16) {
#pragma unroll
            for (int nt = 0; nt < NT; nt++)
                Bb[(kt + 1) & 1][nt] = __ldg(bp + (kt + 1) * 32 + nt * 512);
        }
        const uint2* ar = Asm + (m0 + g) * Ast2 + kt * 8 + t;
        uint2 u0 = ar[0];
        uint2 u1 = ar[8 * Ast2];
        uint2 u2 = ar[4];
        uint2 u3 = ar[8 * Ast2 + 4];
        unsigned Ah[4] = {u0.x, u1.x, u2.x, u3.x};
        unsigned Al[4] = {u0.y, u1.y, u2.y, u3.y};
#pragma unroll
        for (int nt = 0; nt < NT; nt++) {
            uint4 v = Bb[kt & 1][nt];
            mma16816(acc[nt], Ah, v.x, v.y);
            mma16816(acc[nt], Ah, v.z, v.w);
            mma16816(acc[nt], Al, v.x, v.y);
        }
    }

#pragma unroll
    for (int nt = 0; nt < NT; nt++) {
        float c0 = acc[nt][0], c1 = acc[nt][1];
        float c2 = acc[nt][2], c3 = acc[nt][3];
        int r0 = m0 + g, r1 = m0 + g + 8;
        if (OM == 1) {
            int k2o = (outcol0 >> 1) + nt * 4 + t;
            outs[r0 * ost2 + k2o] = split_pack2(c0, c1);
            outs[r1 * ost2 + k2o] = split_pack2(c2, c3);
        } else {
            if (OM == 2) {
                c0 = gelu_exact(c0); c1 = gelu_exact(c1);
                c2 = gelu_exact(c2); c3 = gelu_exact(c3);
            }
            int col = outcol0 + nt * 8 + 2 * t;
            *(float2*)&outf[r0 * ofst + col] = make_float2(c0, c1);
            *(float2*)&outf[r1 * ofst + col] = make_float2(c2, c3);
        }
    }
}

// ---------------------------------------------------------------------------
// Main kernel: 1024 CTAs x 512 threads, 32 windows per CTA.
// ---------------------------------------------------------------------------
__global__ void __launch_bounds__(512, 1)
ach_main(const float* __restrict__ x, const int* __restrict__ mask,
         const float* __restrict__ ipb, const float* __restrict__ out_b,
         const float* __restrict__ ln_g, const float* __restrict__ ln_b,
         const float* __restrict__ b1, const float* __restrict__ w2,
         const float* __restrict__ b2, float* __restrict__ out) {
    extern __shared__ float S[];
    uint2* XA = (uint2*)&S[XA0];
    uint2* BA = (uint2*)&S[BA0];
    const int tid = threadIdx.x;
    const int lane = tid & 31;
    const int wid = tid >> 5;
    const int mi = wid & 1;        // m-tile (rows mi*16..+16)
    const int ng = wid >> 1;       // n-group 0..7
    const int bn0 = blockIdx.x << 5;

    for (int i = tid; i < 1024; i += 512) S[W0 + i] = g_weff[i];
    if (tid < 4) S[W0 + 1024 + tid] = g_ceff[tid];
    __syncthreads();

    // ---- Phase 1: 2 windows per warp — scores, softmax, xbar (split) ----
#pragma unroll
    for (int rep = 0; rep < 2; rep++) {
        const int w = wid * 2 + rep;
        const long bn = (long)bn0 + w;
        const float4* xp = (const float4*)(x + bn * 1536);
        float4 xa[6], xc[6];
#pragma unroll
        for (int t = 0; t < 6; t++) {
            xa[t] = xp[t * 64 + lane];
            xc[t] = xp[t * 64 + 32 + lane];
        }
        int mv = (lane < 6) ? mask[bn * 6 + lane] : 0;
        unsigned mb = __ballot_sync(0xffffffffu, mv != 0) & 0x3fu;
        if (lane == 0) ((int*)S)[MB0 + w] = (int)mb;

        float aw[4][6];
#pragma unroll
        for (int h = 0; h < 4; h++) {
            const float4* wf = (const float4*)&S[W0 + h * 256];
            float4 wa = wf[lane], wc = wf[32 + lane];
            float ce = S[W0 + 1024 + h];
            float sc[6];
#pragma unroll
            for (int t = 0; t < 6; t++) {
                float p = xa[t].x * wa.x + xa[t].y * wa.y + xa[t].z * wa.z +
                          xa[t].w * wa.w + xc[t].x * wc.x + xc[t].y * wc.y +
                          xc[t].z * wc.z + xc[t].w * wc.w;
#pragma unroll
                for (int o = 16; o > 0; o >>= 1)
                    p += __shfl_xor_sync(0xffffffffu, p, o);
                sc[t] = ((mb >> t) & 1u) ? (p + ce) * 0.125f : -1e9f;
            }
            float m = sc[0];
#pragma unroll
            for (int t = 1; t < 6; t++) m = fmaxf(m, sc[t]);
            float s = 0.f;
#pragma unroll
            for (int t = 0; t < 6; t++) { aw[h][t] = expf(sc[t] - m); s += aw[h][t]; }
            float inv = 1.0f / s;
#pragma unroll
            for (int t = 0; t < 6; t++) aw[h][t] *= inv;
        }
#pragma unroll
        for (int h = 0; h < 4; h++) {
            float4 A = make_float4(0.f, 0.f, 0.f, 0.f);
            float4 C = make_float4(0.f, 0.f, 0.f, 0.f);
#pragma unroll
            for (int t = 0; t < 6; t++) {
                float a = aw[h][t];
                A.x += a * xa[t].x; A.y += a * xa[t].y;
                A.z += a * xa[t].z; A.w += a * xa[t].w;
                C.x += a * xc[t].x; C.y += a * xc[t].y;
                C.z += a * xc[t].z; C.w += a * xc[t].w;
            }
            uint2 p0 = split_pack2(A.x, A.y), p1 = split_pack2(A.z, A.w);
            uint2 p2 = split_pack2(C.x, C.y), p3 = split_pack2(C.z, C.w);
            *(uint4*)&XA[w * XST2 + h * 128 + 2 * lane] =
                make_uint4(p0.x, p0.y, p1.x, p1.y);
            *(uint4*)&XA[w * XST2 + h * 128 + 64 + 2 * lane] =
                make_uint4(p2.x, p2.y, p3.x, p3.y);
        }
    }
    __syncthreads();

    // ---- GEMM1 (block-diag by head): xbar -> bufA (split) ----
    gemm_mma<4, 1>(XA + (ng >> 1) * 128, XST2, mi * 16,
                   g_B1, ng * 4, ipb + 512, ng * 32,
                   nullptr, 0, BA, BAST2);
    __syncthreads();
    // ---- GEMM2: bufA -> bufB fp32 ----
    gemm_mma<4, 0>(BA, BAST2, mi * 16, g_B2, ng * 4, out_b, ng * 32,
                   &S[BB0], BBST, nullptr, 0);
    __syncthreads();

    // ---- LayerNorm: bufB fp32 -> bufA (split). Lane owns 8 consecutive ----
#pragma unroll
    for (int rep = 0; rep < 2; rep++) {
        const int w = wid * 2 + rep;
        float4 va = *(const float4*)&S[BB0 + w * BBST + lane * 8];
        float4 vb = *(const float4*)&S[BB0 + w * BBST + lane * 8 + 4];
        float s = va.x + va.y + va.z + va.w + vb.x + vb.y + vb.z + vb.w;
        float s2 = va.x * va.x + va.y * va.y + va.z * va.z + va.w * va.w +
                   vb.x * vb.x + vb.y * vb.y + vb.z * vb.z + vb.w * vb.w;
#pragma unroll
        for (int o = 16; o > 0; o >>= 1) {
            s  += __shfl_xor_sync(0xffffffffu, s, o);
            s2 += __shfl_xor_sync(0xffffffffu, s2, o);
        }
        float mu = s * (1.0f / 256.0f);
        float var = s2 * (1.0f / 256.0f) - mu * mu;
        float rstd = rsqrtf(var + 1e-5f);
        float y[8];
        float vv[8] = {va.x, va.y, va.z, va.w, vb.x, vb.y, vb.z, vb.w};
#pragma unroll
        for (int j = 0; j < 8; j++) {
            int o = lane * 8 + j;
            y[j] = (vv[j] - mu) * rstd * ln_g[o] + ln_b[o];
        }
        uint2 p0 = split_pack2(y[0], y[1]), p1 = split_pack2(y[2], y[3]);
        uint2 p2 = split_pack2(y[4], y[5]), p3 = split_pack2(y[6], y[7]);
        *(uint4*)&BA[w * BAST2 + lane * 4] = make_uint4(p0.x, p0.y, p1.x, p1.y);
        *(uint4*)&BA[w * BAST2 + lane * 4 + 2] = make_uint4(p2.x, p2.y, p3.x, p3.y);
    }
    __syncthreads();

    // ---- GEMM3: fc1 + exact GELU: bufA -> G3 fp32 ----
    gemm_mma<2, 2>(BA, BAST2, mi * 16, g_B3, ng * 2, b1, ng * 16,
                   &S[G30], G3ST, nullptr, 0);
    __syncthreads();

    // ---- Final dot with w2, zero invalid windows ----
#pragma unroll
    for (int rep = 0; rep < 2; rep++) {
        const int w = wid * 2 + rep;
        float r = 0.f;
#pragma unroll
        for (int j = 0; j < 4; j++) {
            int o = lane + 32 * j;
            r += S[G30 + w * G3ST + o] * w2[o];
        }
#pragma unroll
        for (int o = 16; o > 0; o >>= 1)
            r += __shfl_xor_sync(0xffffffffu, r, o);
        if (lane == 0) {
            int mb = ((int*)S)[MB0 + w];
            out[bn0 + w] = mb ? (r + b2[0]) : 0.0f;
        }
    }
}

// ---------------------------------------------------------------------------
extern "C" void kernel_launch(void* const* d_in, const int* in_sizes, int n_in,
                              void* d_out, int out_size) {
    (void)in_sizes; (void)n_in; (void)out_size;
    const float* x    = (const float*)d_in[0];
    const int*   mask = (const int*)d_in[1];
    const float* query= (const float*)d_in[2];
    const float* ipw  = (const float*)d_in[3];
    const float* ipb  = (const float*)d_in[4];
    const float* outw = (const float*)d_in[5];
    const float* outb = (const float*)d_in[6];
    const float* ln_g = (const float*)d_in[7];
    const float* ln_b = (const float*)d_in[8];
    const float* w1   = (const float*)d_in[9];
    const float* b1   = (const float*)d_in[10];
    const float* w2   = (const float*)d_in[11];
    const float* b2   = (const float*)d_in[12];
    float* out = (float*)d_out;

    cudaFuncSetAttribute(ach_main, cudaFuncAttributeMaxDynamicSharedMemorySize,
                         SMEM_BYTES);

    ach_prep0<<<1, 256>>>(query, ipw, ipb);
    ach_prep1<<<160, 256>>>(ipw, outw, w1);
    ach_main<<<1024, 512, SMEM_BYTES>>>(x, mask, ipb, outb, ln_g, ln_b, b1, w2,
                                        b2, out);
}